// round 3
// baseline (speedup 1.0000x reference)
#include <cuda_runtime.h>
#include <math.h>

// Problem constants
#define HIDDEN 2048
#define S_LEN  2048
#define NH     32
#define NKV    8
#define HD     64

// Scratch (no allocations allowed -> device globals)
__device__ float g_q  [S_LEN * NH  * HD];   // 16 MB (raw, un-rotated)
__device__ float g_k  [S_LEN * NKV * HD];   //  4 MB (raw, un-rotated)
__device__ float g_v  [S_LEN * NKV * HD];   //  4 MB
__device__ float g_ctx[S_LEN * NH  * HD];   // 16 MB
__device__ float g_cos[S_LEN * (HD / 2)];   // 256 KB rope tables
__device__ float g_sin[S_LEN * (HD / 2)];

// ---------------------------------------------------------------------------
// SGEMM: C[M,N] = A[M,K] @ B[K,N], all row-major, fp32.
// 64x64 block tile, BK=16, 256 threads, 4x4 per-thread tile.
// ---------------------------------------------------------------------------
#define BM 64
#define BN 64
#define BK 16

__global__ __launch_bounds__(256) void sgemm_kernel(
    const float* __restrict__ A, const float* __restrict__ B,
    float* __restrict__ C, int M, int N, int K)
{
    __shared__ float As[BM][BK + 1];
    __shared__ float Bs[BK][BN];

    const int tid = threadIdx.x;
    const int tx  = tid & 15;
    const int ty  = tid >> 4;
    const int m0  = blockIdx.y * BM;
    const int n0  = blockIdx.x * BN;

    const int am = tid >> 2;           // 0..63
    const int ak = (tid & 3) << 2;     // 0,4,8,12
    const int bk = tid >> 4;           // 0..15
    const int bn = (tid & 15) << 2;    // 0..60

    float acc[4][4] = {};

    for (int k0 = 0; k0 < K; k0 += BK) {
        float4 a4 = *reinterpret_cast<const float4*>(A + (size_t)(m0 + am) * K + k0 + ak);
        As[am][ak + 0] = a4.x; As[am][ak + 1] = a4.y;
        As[am][ak + 2] = a4.z; As[am][ak + 3] = a4.w;

        float4 b4 = *reinterpret_cast<const float4*>(B + (size_t)(k0 + bk) * N + n0 + bn);
        *reinterpret_cast<float4*>(&Bs[bk][bn]) = b4;

        __syncthreads();
#pragma unroll
        for (int k = 0; k < BK; k++) {
            float a[4];
#pragma unroll
            for (int i = 0; i < 4; i++) a[i] = As[ty * 4 + i][k];
            float4 b = *reinterpret_cast<const float4*>(&Bs[k][tx * 4]);
#pragma unroll
            for (int i = 0; i < 4; i++) {
                acc[i][0] += a[i] * b.x;
                acc[i][1] += a[i] * b.y;
                acc[i][2] += a[i] * b.z;
                acc[i][3] += a[i] * b.w;
            }
        }
        __syncthreads();
    }
#pragma unroll
    for (int i = 0; i < 4; i++) {
        float4 r = make_float4(acc[i][0], acc[i][1], acc[i][2], acc[i][3]);
        *reinterpret_cast<float4*>(C + (size_t)(m0 + ty * 4 + i) * N + n0 + tx * 4) = r;
    }
}

// ---------------------------------------------------------------------------
// RoPE cos/sin tables: cos[t][p] = cos(t * theta^-(2p/64)), p = 0..31
// NOTE: CUDA sincosf signature is sincosf(x, &sin, &cos) — SIN FIRST.
// ---------------------------------------------------------------------------
__global__ void rope_table_kernel()
{
    int idx = blockIdx.x * blockDim.x + threadIdx.x;
    if (idx >= S_LEN * (HD / 2)) return;
    int p = idx & 31;
    int t = idx >> 5;
    float inv_freq = (float)exp(-((double)(2 * p) / 64.0) * log(10000.0));
    float ang = (float)t * inv_freq;
    float s, c;
    sincosf(ang, &s, &c);     // (x, sinptr, cosptr) — was swapped before!
    g_cos[idx] = c;
    g_sin[idx] = s;
}

// ---------------------------------------------------------------------------
// Fused flash-style attention with RoPE applied at tile-load time.
// Block = (q-tile of 64 rows, one head). 256 threads, 4x4 per-thread tiles.
// Smem: Qs[64][64], KPs[64][64] (K^T, reused as P), Vs[64][64] = 49152 B
// (fits default 48 KB dynamic smem limit — no attribute opt-in needed).
// ---------------------------------------------------------------------------
#define QT   64
#define KTN  64

__global__ __launch_bounds__(256) void attn_kernel(
    const float* __restrict__ Q, const float* __restrict__ K,
    const float* __restrict__ V, float* __restrict__ O)
{
    extern __shared__ float sm[];
    float* Qs  = sm;            // [r][d] rotated + pre-scaled Q
    float* KPs = sm + 4096;     // [d][c] rotated K^T; later P [r][c]
    float* Vs  = sm + 8192;     // [c][d]

    const int tid = threadIdx.x;
    const int tx  = tid & 15;
    const int ty  = tid >> 4;
    const int h   = blockIdx.y;         // 0..31
    const int q0  = blockIdx.x * QT;
    const int hk  = h >> 2;             // GQA: kv head = h/4

    // Load Q tile, apply RoPE + 1/sqrt(HD) scale
    {
        const int r  = tid >> 2;            // 0..63
        const int dq = (tid & 3) << 2;      // 0,4,8,12
        const int t  = q0 + r;
#pragma unroll
        for (int it = 0; it < 4; it++) {
            int d = dq + it * 16;
            float4 x  = *reinterpret_cast<const float4*>(
                Q + (size_t)t * (NH * HD) + h * HD + d);
            float2 cs = *reinterpret_cast<const float2*>(g_cos + t * 32 + (d >> 1));
            float2 sn = *reinterpret_cast<const float2*>(g_sin + t * 32 + (d >> 1));
            float4 y;
            y.x = (x.x * cs.x - x.y * sn.x) * 0.125f;
            y.y = (x.x * sn.x + x.y * cs.x) * 0.125f;
            y.z = (x.z * cs.y - x.w * sn.y) * 0.125f;
            y.w = (x.z * sn.y + x.w * cs.y) * 0.125f;
            *reinterpret_cast<float4*>(Qs + r * 64 + d) = y;
        }
    }

    float o[4][4] = {};
    float mrow[4], lrow[4];
#pragma unroll
    for (int i = 0; i < 4; i++) { mrow[i] = -1e30f; lrow[i] = 0.f; }

    for (int c0 = 0; c0 < S_LEN; c0 += KTN) {
        __syncthreads();   // prev iter done reading KPs(P)/Vs; Q load on iter 0

        // Load K tile (apply RoPE, store transposed) and V tile
        {
            const int c  = tid >> 2;
            const int dq = (tid & 3) << 2;
            const int t  = c0 + c;
#pragma unroll
            for (int it = 0; it < 4; it++) {
                int d = dq + it * 16;
                float4 x  = *reinterpret_cast<const float4*>(
                    K + (size_t)t * (NKV * HD) + hk * HD + d);
                float2 cs = *reinterpret_cast<const float2*>(g_cos + t * 32 + (d >> 1));
                float2 sn = *reinterpret_cast<const float2*>(g_sin + t * 32 + (d >> 1));
                KPs[(d + 0) * 64 + c] = x.x * cs.x - x.y * sn.x;
                KPs[(d + 1) * 64 + c] = x.x * sn.x + x.y * cs.x;
                KPs[(d + 2) * 64 + c] = x.z * cs.y - x.w * sn.y;
                KPs[(d + 3) * 64 + c] = x.z * sn.y + x.w * cs.y;
                float4 vv = *reinterpret_cast<const float4*>(
                    V + (size_t)t * (NKV * HD) + hk * HD + d);
                *reinterpret_cast<float4*>(Vs + c * 64 + d) = vv;
            }
        }
        __syncthreads();

        // Scores: s[r][c] = Qs[r,:] . K[c,:]  (scale already folded into Qs)
        float s[4][4] = {};
#pragma unroll 8
        for (int d = 0; d < HD; d++) {
            float a[4];
#pragma unroll
            for (int i = 0; i < 4; i++) a[i] = Qs[(ty * 4 + i) * 64 + d];
            float4 b = *reinterpret_cast<const float4*>(KPs + d * 64 + tx * 4);
#pragma unroll
            for (int i = 0; i < 4; i++) {
                s[i][0] += a[i] * b.x; s[i][1] += a[i] * b.y;
                s[i][2] += a[i] * b.z; s[i][3] += a[i] * b.w;
            }
        }
        __syncthreads();   // everyone done reading K^T; buffer becomes P

        // Online softmax update; write P into KPs
#pragma unroll
        for (int i = 0; i < 4; i++) {
            float mx = fmaxf(fmaxf(s[i][0], s[i][1]), fmaxf(s[i][2], s[i][3]));
#pragma unroll
            for (int off = 8; off >= 1; off >>= 1)
                mx = fmaxf(mx, __shfl_xor_sync(0xffffffffu, mx, off));
            float mnew = fmaxf(mrow[i], mx);
            float corr = __expf(mrow[i] - mnew);
            float p0 = __expf(s[i][0] - mnew);
            float p1 = __expf(s[i][1] - mnew);
            float p2 = __expf(s[i][2] - mnew);
            float p3 = __expf(s[i][3] - mnew);
            float rs = p0 + p1 + p2 + p3;
#pragma unroll
            for (int off = 8; off >= 1; off >>= 1)
                rs += __shfl_xor_sync(0xffffffffu, rs, off);
            lrow[i] = lrow[i] * corr + rs;
            mrow[i] = mnew;
#pragma unroll
            for (int j = 0; j < 4; j++) o[i][j] *= corr;
            *reinterpret_cast<float4*>(KPs + (ty * 4 + i) * 64 + tx * 4) =
                make_float4(p0, p1, p2, p3);
        }
        __syncthreads();   // P visible to all before PV

        // O += P @ V
#pragma unroll 8
        for (int c = 0; c < KTN; c++) {
            float a[4];
#pragma unroll
            for (int i = 0; i < 4; i++) a[i] = KPs[(ty * 4 + i) * 64 + c];
            float4 b = *reinterpret_cast<const float4*>(Vs + c * 64 + tx * 4);
#pragma unroll
            for (int i = 0; i < 4; i++) {
                o[i][0] += a[i] * b.x; o[i][1] += a[i] * b.y;
                o[i][2] += a[i] * b.z; o[i][3] += a[i] * b.w;
            }
        }
    }

    // Normalize and write context: ctx[token][h*64 + d]
#pragma unroll
    for (int i = 0; i < 4; i++) {
        float inv = 1.f / lrow[i];
        float4 r = make_float4(o[i][0] * inv, o[i][1] * inv, o[i][2] * inv, o[i][3] * inv);
        *reinterpret_cast<float4*>(
            &O[(size_t)(q0 + ty * 4 + i) * (NH * HD) + h * HD + tx * 4]) = r;
    }
}

// ---------------------------------------------------------------------------
// Launch
// ---------------------------------------------------------------------------
extern "C" void kernel_launch(void* const* d_in, const int* in_sizes, int n_in,
                              void* d_out, int out_size)
{
    const float* X  = (const float*)d_in[0];
    const float* Wq = (const float*)d_in[1];
    const float* Wk = (const float*)d_in[2];
    const float* Wv = (const float*)d_in[3];
    const float* Wo = (const float*)d_in[4];
    float* out = (float*)d_out;

    float *q, *k, *v, *ctx;
    cudaGetSymbolAddress((void**)&q,   g_q);
    cudaGetSymbolAddress((void**)&k,   g_k);
    cudaGetSymbolAddress((void**)&v,   g_v);
    cudaGetSymbolAddress((void**)&ctx, g_ctx);

    // RoPE tables
    rope_table_kernel<<<(S_LEN * (HD / 2) + 255) / 256, 256>>>();

    // QKV projections
    sgemm_kernel<<<dim3((NH * HD) / BN,  S_LEN / BM), 256>>>(X, Wq, q, S_LEN, NH * HD,  HIDDEN);
    sgemm_kernel<<<dim3((NKV * HD) / BN, S_LEN / BM), 256>>>(X, Wk, k, S_LEN, NKV * HD, HIDDEN);
    sgemm_kernel<<<dim3((NKV * HD) / BN, S_LEN / BM), 256>>>(X, Wv, v, S_LEN, NKV * HD, HIDDEN);

    // Fused attention (RoPE applied at load time). 48 KB dynamic smem.
    attn_kernel<<<dim3(S_LEN / QT, NH), 256, 3 * QT * 64 * (int)sizeof(float)>>>(q, k, v, ctx);

    // Output projection
    sgemm_kernel<<<dim3(HIDDEN / BN, S_LEN / BM), 256>>>(ctx, Wo, out, S_LEN, HIDDEN, HIDDEN);
}

// round 5
// speedup vs baseline: 1.6152x; 1.6152x over previous
#include <cuda_runtime.h>
#include <cuda_bf16.h>
#include <cstdint>
#include <math.h>

// ---------------------------------------------------------------------------
// Arch-feature gate: tcgen05 arch-specific instructions (.ld .32x32b, wait,
// fence, dealloc, relinquish) only exist when compiling for sm_10Xa.
// The harness also runs a plain compute_103 pass -> compile a fallback there.
// ---------------------------------------------------------------------------
#if defined(__CUDA_ARCH__)
#  if defined(__CUDA_ARCH_FEAT_SM103_ALL) || defined(__CUDA_ARCH_FEAT_SM100_ALL) || \
      defined(__CUDA_ARCH_FEAT_SM101_ALL)
#    define HAS_TCGEN05 1
#  elif defined(__CUDA_ARCH_HAS_FEATURE__)
#    if __CUDA_ARCH_HAS_FEATURE__(SM103_ALL) || __CUDA_ARCH_HAS_FEATURE__(SM100_ALL)
#      define HAS_TCGEN05 1
#    else
#      define HAS_TCGEN05 0
#    endif
#  else
#    define HAS_TCGEN05 0
#  endif
#else
#  define HAS_TCGEN05 0
#endif

// ---------------------------------------------------------------------------
// Problem constants
// ---------------------------------------------------------------------------
#define HIDDEN 2048
#define S_LEN  2048
#define NH     32
#define NKV    8
#define HD     64
#define NQD    (NH * HD)    // 2048
#define NKVD   (NKV * HD)   // 512

// ---------------------------------------------------------------------------
// Device-global scratch (no allocations allowed)
// ---------------------------------------------------------------------------
__device__ float g_q  [S_LEN * NQD];
__device__ float g_k  [S_LEN * NKVD];
__device__ float g_v  [S_LEN * NKVD];
__device__ float g_ctx[S_LEN * NQD];
__device__ float g_cos[S_LEN * 32];
__device__ float g_sin[S_LEN * 32];

// split-bf16 operands (hi + lo ≈ fp32)
__device__ __nv_bfloat16 g_xhi[S_LEN * HIDDEN], g_xlo[S_LEN * HIDDEN];
__device__ __nv_bfloat16 g_chi[S_LEN * NQD],    g_clo[S_LEN * NQD];
__device__ __nv_bfloat16 g_wqhi[NQD  * HIDDEN], g_wqlo[NQD  * HIDDEN]; // [N][K]
__device__ __nv_bfloat16 g_wkhi[NKVD * HIDDEN], g_wklo[NKVD * HIDDEN];
__device__ __nv_bfloat16 g_wvhi[NKVD * HIDDEN], g_wvlo[NKVD * HIDDEN];
__device__ __nv_bfloat16 g_wohi[HIDDEN * NQD],  g_wolo[HIDDEN * NQD];  // [N][K]

// ---------------------------------------------------------------------------
// PTX helpers (only compiled into the sm_10Xa pass)
// ---------------------------------------------------------------------------
#if HAS_TCGEN05

__device__ __forceinline__ uint32_t smem_u32(const void* p) {
    uint32_t a;
    asm("{ .reg .u64 t; cvta.to.shared.u64 t, %1; cvt.u32.u64 %0, t; }"
        : "=r"(a) : "l"(p));
    return a;
}

__device__ __forceinline__ uint32_t elect_one() {
    uint32_t pred;
    asm volatile("{ .reg .pred p; elect.sync _|p, 0xFFFFFFFF; selp.b32 %0, 1, 0, p; }"
                 : "=r"(pred));
    return pred;
}

#define MBARRIER_INIT(addr, cnt) \
    asm volatile("mbarrier.init.shared.b64 [%0], %1;" :: "r"(addr), "r"(cnt) : "memory")

#define MBARRIER_WAIT_PARITY(mbar, par) do {                                          \
    uint32_t _m = (mbar); uint32_t _p = (par); uint32_t _done;                        \
    asm volatile("{ .reg .pred p; mbarrier.try_wait.parity.acquire.cta.shared::cta.b64 p, [%1], %2;" \
                 " selp.b32 %0, 1, 0, p; }" : "=r"(_done) : "r"(_m), "r"(_p) : "memory"); \
    if (!_done) {                                                                     \
        asm volatile("{ .reg .pred P1; WAIT_LOOP_%=:"                                 \
            " mbarrier.try_wait.parity.acquire.cta.shared::cta.b64 P1, [%0], %1, 0x989680;" \
            " @P1 bra.uni WAIT_DONE_%=; bra.uni WAIT_LOOP_%=; WAIT_DONE_%=: }"        \
            :: "r"(_m), "r"(_p) : "memory");                                          \
    }                                                                                 \
} while (0)

#define TCGEN05_ALLOC(sm_addr, ncols) \
    asm volatile("tcgen05.alloc.cta_group::1.sync.aligned.shared::cta.b32 [%0], %1;" \
                 :: "r"(sm_addr), "r"(ncols) : "memory")
#define TCGEN05_DEALLOC(tm, ncols) \
    asm volatile("tcgen05.dealloc.cta_group::1.sync.aligned.b32 %0, %1;" :: "r"(tm), "r"(ncols))
#define TCGEN05_RELINQ() \
    asm volatile("tcgen05.relinquish_alloc_permit.cta_group::1.sync.aligned;")
#define TCGEN05_COMMIT(mbar) \
    asm volatile("tcgen05.commit.cta_group::1.mbarrier::arrive::one.shared::cluster.b64 [%0];" \
                 :: "r"(mbar) : "memory")
#define TCGEN05_WAIT_LD() asm volatile("tcgen05.wait::ld.sync.aligned;" ::: "memory")
#define TCGEN05_FENCE_AFTER()  asm volatile("tcgen05.fence::after_thread_sync;" ::: "memory")
#define TCGEN05_FENCE_BEFORE() asm volatile("tcgen05.fence::before_thread_sync;" ::: "memory")

#define TCGEN05_LD_X32(r, tm) \
    asm volatile( \
        "tcgen05.ld.sync.aligned.32x32b.x32.b32 " \
        "{%0, %1, %2, %3, %4, %5, %6, %7, %8, %9, %10, %11, %12, %13, %14, %15, " \
        " %16, %17, %18, %19, %20, %21, %22, %23, %24, %25, %26, %27, %28, %29, %30, %31}, [%32];" \
        : "=r"((r)[0]),  "=r"((r)[1]),  "=r"((r)[2]),  "=r"((r)[3]), \
          "=r"((r)[4]),  "=r"((r)[5]),  "=r"((r)[6]),  "=r"((r)[7]), \
          "=r"((r)[8]),  "=r"((r)[9]),  "=r"((r)[10]), "=r"((r)[11]), \
          "=r"((r)[12]), "=r"((r)[13]), "=r"((r)[14]), "=r"((r)[15]), \
          "=r"((r)[16]), "=r"((r)[17]), "=r"((r)[18]), "=r"((r)[19]), \
          "=r"((r)[20]), "=r"((r)[21]), "=r"((r)[22]), "=r"((r)[23]), \
          "=r"((r)[24]), "=r"((r)[25]), "=r"((r)[26]), "=r"((r)[27]), \
          "=r"((r)[28]), "=r"((r)[29]), "=r"((r)[30]), "=r"((r)[31]) \
        : "r"(tm))

// SMEM descriptor, SW128, K-major (LBO=1, SBO=64), Blackwell version=1
__device__ __forceinline__ uint64_t make_desc_sw128(uint32_t addr) {
    return (uint64_t(2) << 61) | (uint64_t(1) << 46) | (uint64_t(64) << 32) |
           (uint64_t(1) << 16) | ((uint64_t)(addr >> 4) & 0x3FFF);
}

// SS cg1 kind::f16 MMA (bf16 in, fp32 accum in TMEM)
__device__ __forceinline__ void mma_bf16_ss(uint32_t d_tmem, uint64_t a_desc,
                                            uint64_t b_desc, uint32_t idesc, uint32_t en) {
    asm volatile(
        "{\n\t.reg .pred p;\n\t"
        "setp.ne.u32 p, %5, 0;\n\t"
        "tcgen05.mma.cta_group::1.kind::f16 [%0], %1, %2, %3, {%4, %4, %4, %4}, p;\n\t"
        "}"
        :: "r"(d_tmem), "l"(a_desc), "l"(b_desc), "r"(idesc), "r"(0u), "r"(en)
        : "memory");
}

// idesc: dtype F32, atype/btype BF16, N=128, M=128
#define GEMM_IDESC ((1u << 4) | (1u << 7) | (1u << 10) | ((128u / 8u) << 17) | ((128u / 16u) << 24))

#endif  // HAS_TCGEN05

// ---------------------------------------------------------------------------
// Split-bf16 conversion kernels
// ---------------------------------------------------------------------------
__global__ void convert_split_kernel(const float* __restrict__ in,
                                     __nv_bfloat16* __restrict__ hi,
                                     __nv_bfloat16* __restrict__ lo, int n)
{
    int i = blockIdx.x * blockDim.x + threadIdx.x;
    if (i >= n) return;
    float x = in[i];
    __nv_bfloat16 h = __float2bfloat16(x);
    hi[i] = h;
    lo[i] = __float2bfloat16(x - __bfloat162float(h));
}

// W[K][N] (row-major) -> hi/lo[N][K]  (transpose + split)
__global__ void convert_wT_kernel(const float* __restrict__ W,
                                  __nv_bfloat16* __restrict__ hi,
                                  __nv_bfloat16* __restrict__ lo, int K, int N)
{
    __shared__ float t[32][33];
    int n0 = blockIdx.x * 32, k0 = blockIdx.y * 32;
    int tx = threadIdx.x, ty = threadIdx.y;  // block (32, 8)
#pragma unroll
    for (int i = ty; i < 32; i += 8)
        t[i][tx] = W[(size_t)(k0 + i) * N + n0 + tx];
    __syncthreads();
#pragma unroll
    for (int i = ty; i < 32; i += 8) {
        float x = t[tx][i];                      // = W[k0+tx][n0+i]
        __nv_bfloat16 h = __float2bfloat16(x);
        size_t o = (size_t)(n0 + i) * K + k0 + tx;
        hi[o] = h;
        lo[o] = __float2bfloat16(x - __bfloat162float(h));
    }
}

// ---------------------------------------------------------------------------
// GEMM: C[M,N] = A[M,K] @ B[N,K]^T, split-bf16 operands, fp32-grade accuracy.
// sm_103a pass: tcgen05, 128x128 tile, K chunk 64, double-buffered.
// plain pass:  FFMA fallback (reconstruct hi+lo), 64x64 tile.
// ---------------------------------------------------------------------------
#define GK 64
#define TILE_B (128 * GK * 2)           // 16384 bytes per bf16 tile
#define STAGE_B (4 * TILE_B)            // 65536
#define GEMM_SMEM (2048 + 2 * STAGE_B)  // slack for 1024-alignment + bars

#if HAS_TCGEN05
__device__ __forceinline__ void load_tile_sw128(char* sdst, const __nv_bfloat16* __restrict__ g,
                                                int row0, int ld, int k0, int tid)
{
    const char* gb = (const char*)(g + (size_t)row0 * ld + k0);
#pragma unroll
    for (int i = 0; i < 4; i++) {
        int v  = i * 256 + tid;          // 0..1023 vectors of 16B
        int r  = v >> 3;                 // row 0..127
        int vc = (v & 7) << 4;           // byte col 0..112
        uint32_t off = r * 128 + vc;
        uint32_t swo = off ^ ((off >> 3) & 0x70);
        uint4 d = *reinterpret_cast<const uint4*>(gb + (size_t)r * (ld * 2) + vc);
        *reinterpret_cast<uint4*>(sdst + swo) = d;
    }
}
#endif

__global__ __launch_bounds__(256, 1) void tc_gemm_kernel(
    const __nv_bfloat16* __restrict__ Ahi, const __nv_bfloat16* __restrict__ Alo,
    const __nv_bfloat16* __restrict__ Bhi, const __nv_bfloat16* __restrict__ Blo,
    float* __restrict__ C, int M, int N, int K)
{
#if HAS_TCGEN05
    extern __shared__ char smem[];
    const uint32_t sb = smem_u32(smem);
    const int tid = threadIdx.x;
    const int wid = tid >> 5;
    const int lid = tid & 31;
    const int m0 = blockIdx.y * 128;
    const int n0 = blockIdx.x * 128;

    const uint32_t BAR0 = sb, BAR1 = sb + 8, TPTR = sb + 16;
    const uint32_t tbase = (sb + 24 + 1023) & ~1023u;
    char* tgen = smem + (tbase - sb);

    if (wid == 0) TCGEN05_ALLOC(TPTR, 128);
    if (tid == 0) { MBARRIER_INIT(BAR0, 1); MBARRIER_INIT(BAR1, 1); }
    __syncthreads();
    uint32_t tmem;
    asm volatile("ld.shared.b32 %0, [%1];" : "=r"(tmem) : "r"(TPTR));

    int ph0 = 0, ph1 = 0;
    const int nchunks = K / GK;

    for (int c = 0; c < nchunks; c++) {
        const int buf = c & 1;
        const uint32_t bar = buf ? BAR1 : BAR0;
        if (c >= 2) {
            if (buf) { MBARRIER_WAIT_PARITY(BAR1, ph1); ph1 ^= 1; }
            else     { MBARRIER_WAIT_PARITY(BAR0, ph0); ph0 ^= 1; }
        }
        char* st = tgen + buf * STAGE_B;
        const int k0 = c * GK;
        load_tile_sw128(st + 0 * TILE_B, Ahi, m0, K, k0, tid);
        load_tile_sw128(st + 1 * TILE_B, Alo, m0, K, k0, tid);
        load_tile_sw128(st + 2 * TILE_B, Bhi, n0, K, k0, tid);
        load_tile_sw128(st + 3 * TILE_B, Blo, n0, K, k0, tid);
        asm volatile("fence.proxy.async.shared::cta;" ::: "memory");
        __syncthreads();

        if (wid == 0 && elect_one()) {
            const uint32_t sa = tbase + buf * STAGE_B;
            uint64_t dAhi = make_desc_sw128(sa + 0 * TILE_B);
            uint64_t dAlo = make_desc_sw128(sa + 1 * TILE_B);
            uint64_t dBhi = make_desc_sw128(sa + 2 * TILE_B);
            uint64_t dBlo = make_desc_sw128(sa + 3 * TILE_B);
            uint64_t da[3] = { dAhi, dAhi, dAlo };
            uint64_t db[3] = { dBhi, dBlo, dBhi };
#pragma unroll
            for (int t = 0; t < 3; t++)
#pragma unroll
                for (int ks = 0; ks < 4; ks++)
                    mma_bf16_ss(tmem, da[t] + ks * 2, db[t] + ks * 2, GEMM_IDESC,
                                (c | t | ks) ? 1u : 0u);
            TCGEN05_COMMIT(bar);
        }
    }

    MBARRIER_WAIT_PARITY(BAR0, ph0);
    MBARRIER_WAIT_PARITY(BAR1, ph1);
    TCGEN05_FENCE_AFTER();

    if (wid < 4) {
        const int m = m0 + wid * 32 + lid;
        float* crow = C + (size_t)m * N + n0;
#pragma unroll
        for (int nb = 0; nb < 4; nb++) {
            uint32_t dreg[32];
            TCGEN05_LD_X32(dreg, tmem + nb * 32);
            TCGEN05_WAIT_LD();
            TCGEN05_FENCE_BEFORE();
            float4* dst = reinterpret_cast<float4*>(crow + nb * 32);
#pragma unroll
            for (int j = 0; j < 8; j++)
                dst[j] = make_float4(__uint_as_float(dreg[4 * j + 0]),
                                     __uint_as_float(dreg[4 * j + 1]),
                                     __uint_as_float(dreg[4 * j + 2]),
                                     __uint_as_float(dreg[4 * j + 3]));
        }
    }
    __syncthreads();
    if (wid == 0) { TCGEN05_RELINQ(); TCGEN05_DEALLOC(tmem, 128); }

#else  // ---------------- FFMA fallback (plain compute_103 pass) ------------
    // Grid was sized for 128x128 tiles; each CTA handles a 128x128 tile as
    // four 64x64 sub-tiles with a 64x64x32 FFMA loop. Correctness-first path.
    __shared__ float As[64][33];
    __shared__ float Bs[64][33];

    const int tid = threadIdx.x;
    const int tx  = tid & 15;
    const int ty  = tid >> 4;

    for (int sub = 0; sub < 4; sub++) {
        const int m0 = blockIdx.y * 128 + (sub >> 1) * 64;
        const int n0 = blockIdx.x * 128 + (sub & 1) * 64;
        float acc[4][4] = {};
        for (int k0 = 0; k0 < K; k0 += 32) {
            __syncthreads();
#pragma unroll
            for (int i = 0; i < 8; i++) {
                int e  = tid * 8 + i;
                int r  = e >> 5;
                int kk = e & 31;
                size_t ai = (size_t)(m0 + r) * K + k0 + kk;
                size_t bi = (size_t)(n0 + r) * K + k0 + kk;
                As[r][kk] = __bfloat162float(Ahi[ai]) + __bfloat162float(Alo[ai]);
                Bs[r][kk] = __bfloat162float(Bhi[bi]) + __bfloat162float(Blo[bi]);
            }
            __syncthreads();
#pragma unroll
            for (int k = 0; k < 32; k++) {
                float a[4], b[4];
#pragma unroll
                for (int i = 0; i < 4; i++) a[i] = As[ty * 4 + i][k];
#pragma unroll
                for (int j = 0; j < 4; j++) b[j] = Bs[tx * 4 + j][k];
#pragma unroll
                for (int i = 0; i < 4; i++)
#pragma unroll
                    for (int j = 0; j < 4; j++) acc[i][j] += a[i] * b[j];
            }
        }
#pragma unroll
        for (int i = 0; i < 4; i++) {
            float4 r = make_float4(acc[i][0], acc[i][1], acc[i][2], acc[i][3]);
            *reinterpret_cast<float4*>(C + (size_t)(m0 + ty * 4 + i) * N + n0 + tx * 4) = r;
        }
        __syncthreads();
    }
#endif
}

// ---------------------------------------------------------------------------
// RoPE tables: sincosf is (x, &sin, &cos) — SIN FIRST.
// ---------------------------------------------------------------------------
__global__ void rope_table_kernel()
{
    int idx = blockIdx.x * blockDim.x + threadIdx.x;
    if (idx >= S_LEN * 32) return;
    int p = idx & 31;
    int t = idx >> 5;
    float inv_freq = (float)exp(-((double)(2 * p) / 64.0) * log(10000.0));
    float ang = (float)t * inv_freq;
    float s, c;
    sincosf(ang, &s, &c);
    g_cos[idx] = c;
    g_sin[idx] = s;
}

// ---------------------------------------------------------------------------
// Fused flash attention (fp32 FFMA) with RoPE at load time.
// ---------------------------------------------------------------------------
#define QT 64

__global__ __launch_bounds__(256) void attn_kernel(
    const float* __restrict__ Q, const float* __restrict__ K,
    const float* __restrict__ V, float* __restrict__ O)
{
    extern __shared__ float sm[];
    float* Qs  = sm;
    float* KPs = sm + 4096;
    float* Vs  = sm + 8192;

    const int tid = threadIdx.x;
    const int tx  = tid & 15;
    const int ty  = tid >> 4;
    const int h   = blockIdx.y;
    const int q0  = blockIdx.x * QT;
    const int hk  = h >> 2;

    {
        const int r  = tid >> 2;
        const int dq = (tid & 3) << 2;
        const int t  = q0 + r;
#pragma unroll
        for (int it = 0; it < 4; it++) {
            int d = dq + it * 16;
            float4 x  = *reinterpret_cast<const float4*>(Q + (size_t)t * NQD + h * HD + d);
            float2 cs = *reinterpret_cast<const float2*>(g_cos + t * 32 + (d >> 1));
            float2 sn = *reinterpret_cast<const float2*>(g_sin + t * 32 + (d >> 1));
            float4 y;
            y.x = (x.x * cs.x - x.y * sn.x) * 0.125f;
            y.y = (x.x * sn.x + x.y * cs.x) * 0.125f;
            y.z = (x.z * cs.y - x.w * sn.y) * 0.125f;
            y.w = (x.z * sn.y + x.w * cs.y) * 0.125f;
            *reinterpret_cast<float4*>(Qs + r * 64 + d) = y;
        }
    }

    float o[4][4] = {};
    float mrow[4], lrow[4];
#pragma unroll
    for (int i = 0; i < 4; i++) { mrow[i] = -1e30f; lrow[i] = 0.f; }

    for (int c0 = 0; c0 < S_LEN; c0 += 64) {
        __syncthreads();
        {
            const int c  = tid >> 2;
            const int dq = (tid & 3) << 2;
            const int t  = c0 + c;
#pragma unroll
            for (int it = 0; it < 4; it++) {
                int d = dq + it * 16;
                float4 x  = *reinterpret_cast<const float4*>(K + (size_t)t * NKVD + hk * HD + d);
                float2 cs = *reinterpret_cast<const float2*>(g_cos + t * 32 + (d >> 1));
                float2 sn = *reinterpret_cast<const float2*>(g_sin + t * 32 + (d >> 1));
                KPs[(d + 0) * 64 + c] = x.x * cs.x - x.y * sn.x;
                KPs[(d + 1) * 64 + c] = x.x * sn.x + x.y * cs.x;
                KPs[(d + 2) * 64 + c] = x.z * cs.y - x.w * sn.y;
                KPs[(d + 3) * 64 + c] = x.z * sn.y + x.w * cs.y;
                float4 vv = *reinterpret_cast<const float4*>(V + (size_t)t * NKVD + hk * HD + d);
                *reinterpret_cast<float4*>(Vs + c * 64 + d) = vv;
            }
        }
        __syncthreads();

        float s[4][4] = {};
#pragma unroll 8
        for (int d = 0; d < HD; d++) {
            float a[4];
#pragma unroll
            for (int i = 0; i < 4; i++) a[i] = Qs[(ty * 4 + i) * 64 + d];
            float4 b = *reinterpret_cast<const float4*>(KPs + d * 64 + tx * 4);
#pragma unroll
            for (int i = 0; i < 4; i++) {
                s[i][0] += a[i] * b.x; s[i][1] += a[i] * b.y;
                s[i][2] += a[i] * b.z; s[i][3] += a[i] * b.w;
            }
        }
        __syncthreads();

#pragma unroll
        for (int i = 0; i < 4; i++) {
            float mx = fmaxf(fmaxf(s[i][0], s[i][1]), fmaxf(s[i][2], s[i][3]));
#pragma unroll
            for (int off = 8; off >= 1; off >>= 1)
                mx = fmaxf(mx, __shfl_xor_sync(0xffffffffu, mx, off));
            float mnew = fmaxf(mrow[i], mx);
            float corr = __expf(mrow[i] - mnew);
            float p0 = __expf(s[i][0] - mnew);
            float p1 = __expf(s[i][1] - mnew);
            float p2 = __expf(s[i][2] - mnew);
            float p3 = __expf(s[i][3] - mnew);
            float rs = p0 + p1 + p2 + p3;
#pragma unroll
            for (int off = 8; off >= 1; off >>= 1)
                rs += __shfl_xor_sync(0xffffffffu, rs, off);
            lrow[i] = lrow[i] * corr + rs;
            mrow[i] = mnew;
#pragma unroll
            for (int j = 0; j < 4; j++) o[i][j] *= corr;
            *reinterpret_cast<float4*>(KPs + (ty * 4 + i) * 64 + tx * 4) =
                make_float4(p0, p1, p2, p3);
        }
        __syncthreads();

#pragma unroll 8
        for (int c = 0; c < 64; c++) {
            float a[4];
#pragma unroll
            for (int i = 0; i < 4; i++) a[i] = KPs[(ty * 4 + i) * 64 + c];
            float4 b = *reinterpret_cast<const float4*>(Vs + c * 64 + tx * 4);
#pragma unroll
            for (int i = 0; i < 4; i++) {
                o[i][0] += a[i] * b.x; o[i][1] += a[i] * b.y;
                o[i][2] += a[i] * b.z; o[i][3] += a[i] * b.w;
            }
        }
    }

#pragma unroll
    for (int i = 0; i < 4; i++) {
        float inv = 1.f / lrow[i];
        float4 r = make_float4(o[i][0] * inv, o[i][1] * inv, o[i][2] * inv, o[i][3] * inv);
        *reinterpret_cast<float4*>(
            &O[(size_t)(q0 + ty * 4 + i) * NQD + h * HD + tx * 4]) = r;
    }
}

// ---------------------------------------------------------------------------
// Launch
// ---------------------------------------------------------------------------
extern "C" void kernel_launch(void* const* d_in, const int* in_sizes, int n_in,
                              void* d_out, int out_size)
{
    const float* X  = (const float*)d_in[0];
    const float* Wq = (const float*)d_in[1];
    const float* Wk = (const float*)d_in[2];
    const float* Wv = (const float*)d_in[3];
    const float* Wo = (const float*)d_in[4];
    float* out = (float*)d_out;

    float *q, *k, *v, *ctx;
    cudaGetSymbolAddress((void**)&q,   g_q);
    cudaGetSymbolAddress((void**)&k,   g_k);
    cudaGetSymbolAddress((void**)&v,   g_v);
    cudaGetSymbolAddress((void**)&ctx, g_ctx);

    __nv_bfloat16 *xhi, *xlo, *chi, *clo;
    __nv_bfloat16 *wqh, *wql, *wkh, *wkl, *wvh, *wvl, *woh, *wol;
    cudaGetSymbolAddress((void**)&xhi, g_xhi); cudaGetSymbolAddress((void**)&xlo, g_xlo);
    cudaGetSymbolAddress((void**)&chi, g_chi); cudaGetSymbolAddress((void**)&clo, g_clo);
    cudaGetSymbolAddress((void**)&wqh, g_wqhi); cudaGetSymbolAddress((void**)&wql, g_wqlo);
    cudaGetSymbolAddress((void**)&wkh, g_wkhi); cudaGetSymbolAddress((void**)&wkl, g_wklo);
    cudaGetSymbolAddress((void**)&wvh, g_wvhi); cudaGetSymbolAddress((void**)&wvl, g_wvlo);
    cudaGetSymbolAddress((void**)&woh, g_wohi); cudaGetSymbolAddress((void**)&wol, g_wolo);

    cudaFuncSetAttribute(tc_gemm_kernel, cudaFuncAttributeMaxDynamicSharedMemorySize, GEMM_SMEM);

    // RoPE tables + operand conversion
    rope_table_kernel<<<(S_LEN * 32 + 255) / 256, 256>>>();
    convert_split_kernel<<<(S_LEN * HIDDEN + 255) / 256, 256>>>(X, xhi, xlo, S_LEN * HIDDEN);
    convert_wT_kernel<<<dim3(NQD  / 32, HIDDEN / 32), dim3(32, 8)>>>(Wq, wqh, wql, HIDDEN, NQD);
    convert_wT_kernel<<<dim3(NKVD / 32, HIDDEN / 32), dim3(32, 8)>>>(Wk, wkh, wkl, HIDDEN, NKVD);
    convert_wT_kernel<<<dim3(NKVD / 32, HIDDEN / 32), dim3(32, 8)>>>(Wv, wvh, wvl, HIDDEN, NKVD);
    convert_wT_kernel<<<dim3(HIDDEN / 32, NQD / 32),  dim3(32, 8)>>>(Wo, woh, wol, NQD, HIDDEN);

    // QKV projections
    tc_gemm_kernel<<<dim3(NQD  / 128, S_LEN / 128), 256, GEMM_SMEM>>>(xhi, xlo, wqh, wql, q, S_LEN, NQD,  HIDDEN);
    tc_gemm_kernel<<<dim3(NKVD / 128, S_LEN / 128), 256, GEMM_SMEM>>>(xhi, xlo, wkh, wkl, k, S_LEN, NKVD, HIDDEN);
    tc_gemm_kernel<<<dim3(NKVD / 128, S_LEN / 128), 256, GEMM_SMEM>>>(xhi, xlo, wvh, wvl, v, S_LEN, NKVD, HIDDEN);

    // Fused attention (fp32)
    attn_kernel<<<dim3(S_LEN / QT, NH), 256, 3 * QT * 64 * (int)sizeof(float)>>>(q, k, v, ctx);

    // Output projection
    convert_split_kernel<<<(S_LEN * NQD + 255) / 256, 256>>>(ctx, chi, clo, S_LEN * NQD);
    tc_gemm_kernel<<<dim3(HIDDEN / 128, S_LEN / 128), 256, GEMM_SMEM>>>(chi, clo, woh, wol, out, S_LEN, HIDDEN, NQD);
}

// round 6
// speedup vs baseline: 3.8051x; 2.3557x over previous
#include <cuda_runtime.h>
#include <cuda_bf16.h>
#include <cstdint>
#include <math.h>

// ---------------------------------------------------------------------------
// Arch-feature gate: tcgen05 arch-specific instrs only exist on sm_10Xa.
// The harness also compiles a plain compute_103 pass -> fallback bodies there.
// (R5 proved the sm_103a cubin is built and selected at runtime.)
// ---------------------------------------------------------------------------
#if defined(__CUDA_ARCH__)
#  if defined(__CUDA_ARCH_FEAT_SM103_ALL) || defined(__CUDA_ARCH_FEAT_SM100_ALL) || \
      defined(__CUDA_ARCH_FEAT_SM101_ALL)
#    define HAS_TCGEN05 1
#  elif defined(__CUDA_ARCH_HAS_FEATURE__)
#    if __CUDA_ARCH_HAS_FEATURE__(SM103_ALL) || __CUDA_ARCH_HAS_FEATURE__(SM100_ALL)
#      define HAS_TCGEN05 1
#    else
#      define HAS_TCGEN05 0
#    endif
#  else
#    define HAS_TCGEN05 0
#  endif
#else
#  define HAS_TCGEN05 0
#endif

// ---------------------------------------------------------------------------
// Problem constants
// ---------------------------------------------------------------------------
#define HIDDEN 2048
#define S_LEN  2048
#define NH     32
#define NKV    8
#define HD     64
#define NQD    (NH * HD)    // 2048
#define NKVD   (NKV * HD)   // 512

// ---------------------------------------------------------------------------
// Device-global scratch (no allocations allowed)
// ---------------------------------------------------------------------------
__device__ float g_q  [S_LEN * NQD];
__device__ float g_k  [S_LEN * NKVD];
__device__ float g_v  [S_LEN * NKVD];
__device__ float g_ctx[S_LEN * NQD];
__device__ float g_cos[S_LEN * 32];
__device__ float g_sin[S_LEN * 32];

// split-bf16 GEMM operands (hi + lo ~= fp32)
__device__ __nv_bfloat16 g_xhi[S_LEN * HIDDEN], g_xlo[S_LEN * HIDDEN];
__device__ __nv_bfloat16 g_chi[S_LEN * NQD],    g_clo[S_LEN * NQD];
__device__ __nv_bfloat16 g_wqhi[NQD  * HIDDEN], g_wqlo[NQD  * HIDDEN]; // [N][K]
__device__ __nv_bfloat16 g_wkhi[NKVD * HIDDEN], g_wklo[NKVD * HIDDEN];
__device__ __nv_bfloat16 g_wvhi[NKVD * HIDDEN], g_wvlo[NKVD * HIDDEN];
__device__ __nv_bfloat16 g_wohi[HIDDEN * NQD],  g_wolo[HIDDEN * NQD];  // [N][K]

// split-bf16 attention operands (rotated, Q pre-scaled by 1/8)
__device__ __nv_bfloat16 g_qshi[S_LEN * NQD],  g_qslo[S_LEN * NQD];
__device__ __nv_bfloat16 g_kshi[S_LEN * NKVD], g_kslo[S_LEN * NKVD];
__device__ __nv_bfloat16 g_vthi[NKVD * S_LEN], g_vtlo[NKVD * S_LEN];  // [hk*64+d][t]

// ---------------------------------------------------------------------------
// PTX helpers (sm_10Xa pass only)
// ---------------------------------------------------------------------------
#if HAS_TCGEN05

__device__ __forceinline__ uint32_t smem_u32(const void* p) {
    uint32_t a;
    asm("{ .reg .u64 t; cvta.to.shared.u64 t, %1; cvt.u32.u64 %0, t; }"
        : "=r"(a) : "l"(p));
    return a;
}

__device__ __forceinline__ uint32_t elect_one() {
    uint32_t pred;
    asm volatile("{ .reg .pred p; elect.sync _|p, 0xFFFFFFFF; selp.b32 %0, 1, 0, p; }"
                 : "=r"(pred));
    return pred;
}

#define MBARRIER_INIT(addr, cnt) \
    asm volatile("mbarrier.init.shared.b64 [%0], %1;" :: "r"(addr), "r"(cnt) : "memory")

#define MBARRIER_WAIT_PARITY(mbar, par) do {                                          \
    uint32_t _m = (mbar); uint32_t _p = (par); uint32_t _done;                        \
    asm volatile("{ .reg .pred p; mbarrier.try_wait.parity.acquire.cta.shared::cta.b64 p, [%1], %2;" \
                 " selp.b32 %0, 1, 0, p; }" : "=r"(_done) : "r"(_m), "r"(_p) : "memory"); \
    if (!_done) {                                                                     \
        asm volatile("{ .reg .pred P1; WAIT_LOOP_%=:"                                 \
            " mbarrier.try_wait.parity.acquire.cta.shared::cta.b64 P1, [%0], %1, 0x989680;" \
            " @P1 bra.uni WAIT_DONE_%=; bra.uni WAIT_LOOP_%=; WAIT_DONE_%=: }"        \
            :: "r"(_m), "r"(_p) : "memory");                                          \
    }                                                                                 \
} while (0)

#define TCGEN05_ALLOC(sm_addr, ncols) \
    asm volatile("tcgen05.alloc.cta_group::1.sync.aligned.shared::cta.b32 [%0], %1;" \
                 :: "r"(sm_addr), "r"(ncols) : "memory")
#define TCGEN05_DEALLOC(tm, ncols) \
    asm volatile("tcgen05.dealloc.cta_group::1.sync.aligned.b32 %0, %1;" :: "r"(tm), "r"(ncols))
#define TCGEN05_RELINQ() \
    asm volatile("tcgen05.relinquish_alloc_permit.cta_group::1.sync.aligned;")
#define TCGEN05_COMMIT(mbar) \
    asm volatile("tcgen05.commit.cta_group::1.mbarrier::arrive::one.shared::cluster.b64 [%0];" \
                 :: "r"(mbar) : "memory")
#define TCGEN05_WAIT_LD() asm volatile("tcgen05.wait::ld.sync.aligned;" ::: "memory")
#define TCGEN05_FENCE_AFTER()  asm volatile("tcgen05.fence::after_thread_sync;" ::: "memory")
#define TCGEN05_FENCE_BEFORE() asm volatile("tcgen05.fence::before_thread_sync;" ::: "memory")
#define FENCE_ASYNC() asm volatile("fence.proxy.async.shared::cta;" ::: "memory")

#define TCGEN05_LD_X32(r, tm) \
    asm volatile( \
        "tcgen05.ld.sync.aligned.32x32b.x32.b32 " \
        "{%0, %1, %2, %3, %4, %5, %6, %7, %8, %9, %10, %11, %12, %13, %14, %15, " \
        " %16, %17, %18, %19, %20, %21, %22, %23, %24, %25, %26, %27, %28, %29, %30, %31}, [%32];" \
        : "=r"((r)[0]),  "=r"((r)[1]),  "=r"((r)[2]),  "=r"((r)[3]), \
          "=r"((r)[4]),  "=r"((r)[5]),  "=r"((r)[6]),  "=r"((r)[7]), \
          "=r"((r)[8]),  "=r"((r)[9]),  "=r"((r)[10]), "=r"((r)[11]), \
          "=r"((r)[12]), "=r"((r)[13]), "=r"((r)[14]), "=r"((r)[15]), \
          "=r"((r)[16]), "=r"((r)[17]), "=r"((r)[18]), "=r"((r)[19]), \
          "=r"((r)[20]), "=r"((r)[21]), "=r"((r)[22]), "=r"((r)[23]), \
          "=r"((r)[24]), "=r"((r)[25]), "=r"((r)[26]), "=r"((r)[27]), \
          "=r"((r)[28]), "=r"((r)[29]), "=r"((r)[30]), "=r"((r)[31]) \
        : "r"(tm))

__device__ __forceinline__ uint64_t make_desc_sw128(uint32_t addr) {
    return (uint64_t(2) << 61) | (uint64_t(1) << 46) | (uint64_t(64) << 32) |
           (uint64_t(1) << 16) | ((uint64_t)(addr >> 4) & 0x3FFF);
}

__device__ __forceinline__ void mma_bf16_ss(uint32_t d_tmem, uint64_t a_desc,
                                            uint64_t b_desc, uint32_t idesc, uint32_t en) {
    asm volatile(
        "{\n\t.reg .pred p;\n\t"
        "setp.ne.u32 p, %5, 0;\n\t"
        "tcgen05.mma.cta_group::1.kind::f16 [%0], %1, %2, %3, {%4, %4, %4, %4}, p;\n\t"
        "}"
        :: "r"(d_tmem), "l"(a_desc), "l"(b_desc), "r"(idesc), "r"(0u), "r"(en)
        : "memory");
}

// idescs: dtype F32, a/b BF16
#define GEMM_IDESC ((1u << 4) | (1u << 7) | (1u << 10) | ((128u / 8u) << 17) | ((128u / 16u) << 24))
#define PV_IDESC   ((1u << 4) | (1u << 7) | (1u << 10) | ((64u  / 8u) << 17) | ((128u / 16u) << 24))

#endif  // HAS_TCGEN05

// ---------------------------------------------------------------------------
// Conversion / prep kernels (arch-independent)
// ---------------------------------------------------------------------------
__global__ void convert_split_kernel(const float* __restrict__ in,
                                     __nv_bfloat16* __restrict__ hi,
                                     __nv_bfloat16* __restrict__ lo, int n)
{
    int i = blockIdx.x * blockDim.x + threadIdx.x;
    if (i >= n) return;
    float x = in[i];
    __nv_bfloat16 h = __float2bfloat16(x);
    hi[i] = h;
    lo[i] = __float2bfloat16(x - __bfloat162float(h));
}

// W[K][N] -> hi/lo[N][K]  (transpose + split)
__global__ void convert_wT_kernel(const float* __restrict__ W,
                                  __nv_bfloat16* __restrict__ hi,
                                  __nv_bfloat16* __restrict__ lo, int K, int N)
{
    __shared__ float t[32][33];
    int n0 = blockIdx.x * 32, k0 = blockIdx.y * 32;
    int tx = threadIdx.x, ty = threadIdx.y;  // block (32, 8)
#pragma unroll
    for (int i = ty; i < 32; i += 8)
        t[i][tx] = W[(size_t)(k0 + i) * N + n0 + tx];
    __syncthreads();
#pragma unroll
    for (int i = ty; i < 32; i += 8) {
        float x = t[tx][i];
        __nv_bfloat16 h = __float2bfloat16(x);
        size_t o = (size_t)(n0 + i) * K + k0 + tx;
        hi[o] = h;
        lo[o] = __float2bfloat16(x - __bfloat162float(h));
    }
}

// RoPE tables. sincosf is (x, &sin, &cos) — SIN FIRST.
__global__ void rope_table_kernel()
{
    int idx = blockIdx.x * blockDim.x + threadIdx.x;
    if (idx >= S_LEN * 32) return;
    int p = idx & 31;
    int t = idx >> 5;
    float inv_freq = (float)exp(-((double)(2 * p) / 64.0) * log(10000.0));
    float ang = (float)t * inv_freq;
    float s, c;
    sincosf(ang, &s, &c);
    g_cos[idx] = c;
    g_sin[idx] = s;
}

// rotate (+optional scale) + split to bf16 hi/lo. W = row width (2048 or 512).
__global__ void prep_rope_split_kernel(const float* __restrict__ src,
                                       __nv_bfloat16* __restrict__ hi,
                                       __nv_bfloat16* __restrict__ lo,
                                       int W, float scale, int n_pairs)
{
    int idx = blockIdx.x * blockDim.x + threadIdx.x;
    if (idx >= n_pairs) return;
    int wp  = W >> 1;
    int t   = idx / wp;
    int cp  = idx % wp;
    int col = cp * 2;
    int p   = (col & 63) >> 1;
    float c = g_cos[t * 32 + p];
    float s = g_sin[t * 32 + p];
    float xe = src[(size_t)t * W + col];
    float xo = src[(size_t)t * W + col + 1];
    float ye = (xe * c - xo * s) * scale;
    float yo = (xe * s + xo * c) * scale;
    __nv_bfloat16 he = __float2bfloat16(ye);
    __nv_bfloat16 ho = __float2bfloat16(yo);
    size_t o = (size_t)t * W + col;
    hi[o]     = he;  lo[o]     = __float2bfloat16(ye - __bfloat162float(he));
    hi[o + 1] = ho;  lo[o + 1] = __float2bfloat16(yo - __bfloat162float(ho));
}

// V[t][c] (c = hk*64+d, 512 wide) -> Vt[c][t] split bf16
__global__ void prep_vt_kernel(const float* __restrict__ V,
                               __nv_bfloat16* __restrict__ hi,
                               __nv_bfloat16* __restrict__ lo)
{
    __shared__ float tile[32][33];
    int c0 = blockIdx.x * 32;   // 0..511
    int t0 = blockIdx.y * 32;   // 0..2047
    int tx = threadIdx.x, ty = threadIdx.y;  // (32, 8)
#pragma unroll
    for (int i = ty; i < 32; i += 8)
        tile[i][tx] = V[(size_t)(t0 + i) * NKVD + c0 + tx];
    __syncthreads();
#pragma unroll
    for (int i = ty; i < 32; i += 8) {
        float x = tile[tx][i];                   // = V[t0+tx][c0+i]
        __nv_bfloat16 h = __float2bfloat16(x);
        size_t o = (size_t)(c0 + i) * S_LEN + t0 + tx;
        hi[o] = h;
        lo[o] = __float2bfloat16(x - __bfloat162float(h));
    }
}

// ---------------------------------------------------------------------------
// tcgen05 split-bf16 GEMM (unchanged from R5): C[M,N] = A[M,K] @ B[N,K]^T
// ---------------------------------------------------------------------------
#define GK 64
#define TILE_B (128 * GK * 2)
#define STAGE_B (4 * TILE_B)
#define GEMM_SMEM (2048 + 2 * STAGE_B)

#if HAS_TCGEN05
__device__ __forceinline__ void load_tile_sw128(char* sdst, const __nv_bfloat16* __restrict__ g,
                                                int row0, int ld, int k0, int tid)
{
    const char* gb = (const char*)(g + (size_t)row0 * ld + k0);
#pragma unroll
    for (int i = 0; i < 4; i++) {
        int v  = i * 256 + tid;
        int r  = v >> 3;
        int vc = (v & 7) << 4;
        uint32_t off = r * 128 + vc;
        uint32_t swo = off ^ ((off >> 3) & 0x70);
        uint4 d = *reinterpret_cast<const uint4*>(gb + (size_t)r * (ld * 2) + vc);
        *reinterpret_cast<uint4*>(sdst + swo) = d;
    }
}
#endif

__global__ __launch_bounds__(256, 1) void tc_gemm_kernel(
    const __nv_bfloat16* __restrict__ Ahi, const __nv_bfloat16* __restrict__ Alo,
    const __nv_bfloat16* __restrict__ Bhi, const __nv_bfloat16* __restrict__ Blo,
    float* __restrict__ C, int M, int N, int K)
{
#if HAS_TCGEN05
    extern __shared__ char smem[];
    const uint32_t sb = smem_u32(smem);
    const int tid = threadIdx.x;
    const int wid = tid >> 5;
    const int lid = tid & 31;
    const int m0 = blockIdx.y * 128;
    const int n0 = blockIdx.x * 128;

    const uint32_t BAR0 = sb, BAR1 = sb + 8, TPTR = sb + 16;
    const uint32_t tbase = (sb + 24 + 1023) & ~1023u;
    char* tgen = smem + (tbase - sb);

    if (wid == 0) TCGEN05_ALLOC(TPTR, 128);
    if (tid == 0) { MBARRIER_INIT(BAR0, 1); MBARRIER_INIT(BAR1, 1); }
    __syncthreads();
    uint32_t tmem;
    asm volatile("ld.shared.b32 %0, [%1];" : "=r"(tmem) : "r"(TPTR));

    int ph0 = 0, ph1 = 0;
    const int nchunks = K / GK;

    for (int c = 0; c < nchunks; c++) {
        const int buf = c & 1;
        const uint32_t bar = buf ? BAR1 : BAR0;
        if (c >= 2) {
            if (buf) { MBARRIER_WAIT_PARITY(BAR1, ph1); ph1 ^= 1; }
            else     { MBARRIER_WAIT_PARITY(BAR0, ph0); ph0 ^= 1; }
        }
        char* st = tgen + buf * STAGE_B;
        const int k0 = c * GK;
        load_tile_sw128(st + 0 * TILE_B, Ahi, m0, K, k0, tid);
        load_tile_sw128(st + 1 * TILE_B, Alo, m0, K, k0, tid);
        load_tile_sw128(st + 2 * TILE_B, Bhi, n0, K, k0, tid);
        load_tile_sw128(st + 3 * TILE_B, Blo, n0, K, k0, tid);
        FENCE_ASYNC();
        __syncthreads();

        if (wid == 0 && elect_one()) {
            const uint32_t sa = tbase + buf * STAGE_B;
            uint64_t dAhi = make_desc_sw128(sa + 0 * TILE_B);
            uint64_t dAlo = make_desc_sw128(sa + 1 * TILE_B);
            uint64_t dBhi = make_desc_sw128(sa + 2 * TILE_B);
            uint64_t dBlo = make_desc_sw128(sa + 3 * TILE_B);
            uint64_t da[3] = { dAhi, dAhi, dAlo };
            uint64_t db[3] = { dBhi, dBlo, dBhi };
#pragma unroll
            for (int t = 0; t < 3; t++)
#pragma unroll
                for (int ks = 0; ks < 4; ks++)
                    mma_bf16_ss(tmem, da[t] + ks * 2, db[t] + ks * 2, GEMM_IDESC,
                                (c | t | ks) ? 1u : 0u);
            TCGEN05_COMMIT(bar);
        }
    }

    MBARRIER_WAIT_PARITY(BAR0, ph0);
    MBARRIER_WAIT_PARITY(BAR1, ph1);
    TCGEN05_FENCE_AFTER();

    if (wid < 4) {
        const int m = m0 + wid * 32 + lid;
        float* crow = C + (size_t)m * N + n0;
#pragma unroll
        for (int nb = 0; nb < 4; nb++) {
            uint32_t dreg[32];
            TCGEN05_LD_X32(dreg, tmem + nb * 32);
            TCGEN05_WAIT_LD();
            TCGEN05_FENCE_BEFORE();
            float4* dst = reinterpret_cast<float4*>(crow + nb * 32);
#pragma unroll
            for (int j = 0; j < 8; j++)
                dst[j] = make_float4(__uint_as_float(dreg[4 * j + 0]),
                                     __uint_as_float(dreg[4 * j + 1]),
                                     __uint_as_float(dreg[4 * j + 2]),
                                     __uint_as_float(dreg[4 * j + 3]));
        }
    }
    __syncthreads();
    if (wid == 0) { TCGEN05_RELINQ(); TCGEN05_DEALLOC(tmem, 128); }

#else  // FFMA fallback (plain pass; never selected at runtime)
    __shared__ float As[64][33];
    __shared__ float Bs[64][33];
    const int tid = threadIdx.x;
    const int tx  = tid & 15;
    const int ty  = tid >> 4;
    for (int sub = 0; sub < 4; sub++) {
        const int m0 = blockIdx.y * 128 + (sub >> 1) * 64;
        const int n0 = blockIdx.x * 128 + (sub & 1) * 64;
        float acc[4][4] = {};
        for (int k0 = 0; k0 < K; k0 += 32) {
            __syncthreads();
#pragma unroll
            for (int i = 0; i < 8; i++) {
                int e  = tid * 8 + i;
                int r  = e >> 5;
                int kk = e & 31;
                size_t ai = (size_t)(m0 + r) * K + k0 + kk;
                size_t bi = (size_t)(n0 + r) * K + k0 + kk;
                As[r][kk] = __bfloat162float(Ahi[ai]) + __bfloat162float(Alo[ai]);
                Bs[r][kk] = __bfloat162float(Bhi[bi]) + __bfloat162float(Blo[bi]);
            }
            __syncthreads();
#pragma unroll
            for (int k = 0; k < 32; k++) {
                float a[4], b[4];
#pragma unroll
                for (int i = 0; i < 4; i++) a[i] = As[ty * 4 + i][k];
#pragma unroll
                for (int j = 0; j < 4; j++) b[j] = Bs[tx * 4 + j][k];
#pragma unroll
                for (int i = 0; i < 4; i++)
#pragma unroll
                    for (int j = 0; j < 4; j++) acc[i][j] += a[i] * b[j];
            }
        }
#pragma unroll
        for (int i = 0; i < 4; i++) {
            float4 r = make_float4(acc[i][0], acc[i][1], acc[i][2], acc[i][3]);
            *reinterpret_cast<float4*>(C + (size_t)(m0 + ty * 4 + i) * N + n0 + tx * 4) = r;
        }
        __syncthreads();
    }
#endif
}

// ---------------------------------------------------------------------------
// tcgen05 flash attention. CTA = (128 q rows, 1 head). 256 threads.
// S (128x128 fp32) and O (128x64 fp32) in TMEM; softmax without running max
// (scores bounded; exp(s) safe in fp32); O accumulates across all K tiles.
// ---------------------------------------------------------------------------
// smem tile byte offsets (within 1024-aligned tile region)
#define A_QHI   0
#define A_QLO   16384
#define A_KHI   32768
#define A_KLO   49152
#define A_VTHI  65536    // two halves: +0 (keys 0-63), +8192 (keys 64-127)
#define A_VTLO  81920
#define A_PHI   98304    // two halves: +0, +16384
#define A_PLO   131072
#define A_TILES_BYTES 163840
#define ATT_SMEM (2112 + 1024 + A_TILES_BYTES)   // header+lpart + align slack + tiles

__global__ __launch_bounds__(256, 1) void attn_tc_kernel(
    const __nv_bfloat16* __restrict__ Qhi, const __nv_bfloat16* __restrict__ Qlo,
    const __nv_bfloat16* __restrict__ Khi, const __nv_bfloat16* __restrict__ Klo,
    const __nv_bfloat16* __restrict__ Vthi, const __nv_bfloat16* __restrict__ Vtlo,
    float* __restrict__ O)
{
#if HAS_TCGEN05
    extern __shared__ char smem[];
    const uint32_t sb = smem_u32(smem);
    const int tid = threadIdx.x;
    const int wid = tid >> 5;
    const int lid = tid & 31;
    const int h   = blockIdx.y;
    const int q0  = blockIdx.x * 128;
    const int hk  = h >> 2;

    const uint32_t SBAR = sb, PVBAR = sb + 8, TPTR = sb + 16;
    float* lpart = reinterpret_cast<float*>(smem + 32);   // [2][128] floats
    const uint32_t tbase = (sb + 32 + 1024 + 1023) & ~1023u;
    char* tgen = smem + (tbase - sb);

    if (wid == 0) TCGEN05_ALLOC(TPTR, 256);
    if (tid == 0) { MBARRIER_INIT(SBAR, 1); MBARRIER_INIT(PVBAR, 1); }
    __syncthreads();
    uint32_t tmem;
    asm volatile("ld.shared.b32 %0, [%1];" : "=r"(tmem) : "r"(TPTR));
    const uint32_t tm_S = tmem;          // cols 0-127
    const uint32_t tm_O = tmem + 128;    // cols 128-191

    // ---- prologue: load Q tiles (rotated+scaled, split) ----
    {
        const char* ghi = (const char*)(Qhi + (size_t)q0 * NQD + h * HD);
        const char* glo = (const char*)(Qlo + (size_t)q0 * NQD + h * HD);
#pragma unroll
        for (int i = 0; i < 4; i++) {
            int v = i * 256 + tid;            // 0..1023
            int r = v >> 3;
            int vc = (v & 7) << 4;
            uint32_t off = r * 128 + vc;
            uint32_t swo = off ^ ((off >> 3) & 0x70);
            *reinterpret_cast<uint4*>(tgen + A_QHI + swo) =
                *reinterpret_cast<const uint4*>(ghi + (size_t)r * (NQD * 2) + vc);
            *reinterpret_cast<uint4*>(tgen + A_QLO + swo) =
                *reinterpret_cast<const uint4*>(glo + (size_t)r * (NQD * 2) + vc);
        }
    }

    const int srow = (wid & 3) * 32 + lid;   // this lane's S/O row
    const int chalf = wid >> 2;              // column half (0: keys 0-63, 1: 64-127)
    float l_part = 0.f;

    int ph_s = 0, ph_pv = 0;
    const int NIT = S_LEN / 128;             // 16

    for (int it = 0; it < NIT; it++) {
        const int c0 = it * 128;
        if (it > 0) { MBARRIER_WAIT_PARITY(PVBAR, ph_pv); ph_pv ^= 1; }

        // ---- load K tiles (rows = keys) ----
        {
            const char* ghi = (const char*)(Khi + (size_t)c0 * NKVD + hk * HD);
            const char* glo = (const char*)(Klo + (size_t)c0 * NKVD + hk * HD);
#pragma unroll
            for (int i = 0; i < 4; i++) {
                int v = i * 256 + tid;
                int r = v >> 3;
                int vc = (v & 7) << 4;
                uint32_t off = r * 128 + vc;
                uint32_t swo = off ^ ((off >> 3) & 0x70);
                *reinterpret_cast<uint4*>(tgen + A_KHI + swo) =
                    *reinterpret_cast<const uint4*>(ghi + (size_t)r * (NKVD * 2) + vc);
                *reinterpret_cast<uint4*>(tgen + A_KLO + swo) =
                    *reinterpret_cast<const uint4*>(glo + (size_t)r * (NKVD * 2) + vc);
            }
        }
        // ---- load V^T tiles (rows = d, two 64-key halves) ----
        {
            const char* ghi = (const char*)(Vthi + (size_t)hk * HD * S_LEN + c0);
            const char* glo = (const char*)(Vtlo + (size_t)hk * HD * S_LEN + c0);
#pragma unroll
            for (int i = 0; i < 4; i++) {
                int v = i * 256 + tid;        // 0..1023
                int hf = v >> 9;              // half
                int w  = v & 511;
                int d  = w >> 3;
                int vc = (w & 7) << 4;
                uint32_t off = d * 128 + vc;
                uint32_t swo = off ^ ((off >> 3) & 0x70);
                size_t gof = (size_t)d * (S_LEN * 2) + hf * 128 + vc;
                *reinterpret_cast<uint4*>(tgen + A_VTHI + hf * 8192 + swo) =
                    *reinterpret_cast<const uint4*>(ghi + gof);
                *reinterpret_cast<uint4*>(tgen + A_VTLO + hf * 8192 + swo) =
                    *reinterpret_cast<const uint4*>(glo + gof);
            }
        }
        FENCE_ASYNC();
        __syncthreads();

        // ---- QK^T MMAs -> S ----
        if (wid == 0 && elect_one()) {
            uint64_t dQhi = make_desc_sw128(tbase + A_QHI);
            uint64_t dQlo = make_desc_sw128(tbase + A_QLO);
            uint64_t dKhi = make_desc_sw128(tbase + A_KHI);
            uint64_t dKlo = make_desc_sw128(tbase + A_KLO);
            uint64_t da[3] = { dQhi, dQhi, dQlo };
            uint64_t db[3] = { dKhi, dKlo, dKhi };
#pragma unroll
            for (int t = 0; t < 3; t++)
#pragma unroll
                for (int ks = 0; ks < 4; ks++)
                    mma_bf16_ss(tm_S, da[t] + ks * 2, db[t] + ks * 2, GEMM_IDESC,
                                (t | ks) ? 1u : 0u);
            TCGEN05_COMMIT(SBAR);
        }
        MBARRIER_WAIT_PARITY(SBAR, ph_s); ph_s ^= 1;
        TCGEN05_FENCE_AFTER();

        // ---- softmax (no max-subtraction) + split-bf16 P, per 32-col chunk ----
#pragma unroll
        for (int ch = 0; ch < 2; ch++) {
            uint32_t sreg[32];
            TCGEN05_LD_X32(sreg, tm_S + chalf * 64 + ch * 32);
            TCGEN05_WAIT_LD();
            uint32_t hp[16], lp[16];
            float lsum = 0.f;
#pragma unroll
            for (int j = 0; j < 16; j++) {
                float p0 = __expf(__uint_as_float(sreg[2 * j]));
                float p1 = __expf(__uint_as_float(sreg[2 * j + 1]));
                lsum += p0 + p1;
                __nv_bfloat16 h0 = __float2bfloat16(p0);
                __nv_bfloat16 h1 = __float2bfloat16(p1);
                float r0 = p0 - __bfloat162float(h0);
                float r1 = p1 - __bfloat162float(h1);
                __nv_bfloat16 g0 = __float2bfloat16(r0);
                __nv_bfloat16 g1 = __float2bfloat16(r1);
                hp[j] = (uint32_t)__bfloat16_as_ushort(h0) |
                        ((uint32_t)__bfloat16_as_ushort(h1) << 16);
                lp[j] = (uint32_t)__bfloat16_as_ushort(g0) |
                        ((uint32_t)__bfloat16_as_ushort(g1) << 16);
            }
            l_part += lsum;
            // store to P tiles (row = srow, bytes [ch*64, ch*64+63])
#pragma unroll
            for (int qb = 0; qb < 4; qb++) {
                uint32_t off = srow * 128 + ch * 64 + qb * 16;
                uint32_t swo = off ^ ((off >> 3) & 0x70);
                *reinterpret_cast<uint4*>(tgen + A_PHI + chalf * 16384 + swo) =
                    make_uint4(hp[4 * qb], hp[4 * qb + 1], hp[4 * qb + 2], hp[4 * qb + 3]);
                *reinterpret_cast<uint4*>(tgen + A_PLO + chalf * 16384 + swo) =
                    make_uint4(lp[4 * qb], lp[4 * qb + 1], lp[4 * qb + 2], lp[4 * qb + 3]);
            }
        }
        FENCE_ASYNC();
        __syncthreads();

        // ---- PV MMAs -> O (accumulate across iterations) ----
        if (wid == 0 && elect_one()) {
#pragma unroll
            for (int hf = 0; hf < 2; hf++) {
                uint64_t dPhi = make_desc_sw128(tbase + A_PHI + hf * 16384);
                uint64_t dPlo = make_desc_sw128(tbase + A_PLO + hf * 16384);
                uint64_t dVhi = make_desc_sw128(tbase + A_VTHI + hf * 8192);
                uint64_t dVlo = make_desc_sw128(tbase + A_VTLO + hf * 8192);
                uint64_t da[3] = { dPhi, dPhi, dPlo };
                uint64_t db[3] = { dVhi, dVlo, dVhi };
#pragma unroll
                for (int t = 0; t < 3; t++)
#pragma unroll
                    for (int ks = 0; ks < 4; ks++)
                        mma_bf16_ss(tm_O, da[t] + ks * 2, db[t] + ks * 2, PV_IDESC,
                                    (it | hf | t | ks) ? 1u : 0u);
            }
            TCGEN05_COMMIT(PVBAR);
        }
    }

    MBARRIER_WAIT_PARITY(PVBAR, ph_pv);
    TCGEN05_FENCE_AFTER();

    // ---- epilogue: combine l halves, normalize O, store ctx ----
    lpart[chalf * 128 + srow] = l_part;
    __syncthreads();
    if (wid < 4) {
        const int r = wid * 32 + lid;
        float inv = 1.f / (lpart[r] + lpart[128 + r]);
        uint32_t o0[32], o1[32];
        TCGEN05_LD_X32(o0, tm_O);
        TCGEN05_LD_X32(o1, tm_O + 32);
        TCGEN05_WAIT_LD();
        TCGEN05_FENCE_BEFORE();
        float* dst = O + (size_t)(q0 + r) * NQD + h * HD;
#pragma unroll
        for (int j = 0; j < 8; j++) {
            reinterpret_cast<float4*>(dst)[j] =
                make_float4(__uint_as_float(o0[4 * j + 0]) * inv,
                            __uint_as_float(o0[4 * j + 1]) * inv,
                            __uint_as_float(o0[4 * j + 2]) * inv,
                            __uint_as_float(o0[4 * j + 3]) * inv);
            reinterpret_cast<float4*>(dst)[8 + j] =
                make_float4(__uint_as_float(o1[4 * j + 0]) * inv,
                            __uint_as_float(o1[4 * j + 1]) * inv,
                            __uint_as_float(o1[4 * j + 2]) * inv,
                            __uint_as_float(o1[4 * j + 3]) * inv);
        }
    }
    __syncthreads();
    if (wid == 0) { TCGEN05_RELINQ(); TCGEN05_DEALLOC(tmem, 256); }

#else  // --------- slow but correct fallback (plain pass; never selected) ----
    const int tid = threadIdx.x;
    if (tid >= 128) return;
    const int h  = blockIdx.y;
    const int hk = h >> 2;
    const int t  = blockIdx.x * 128 + tid;
    float qv[64], o[64];
#pragma unroll
    for (int d = 0; d < 64; d++) {
        size_t qi = (size_t)t * NQD + h * HD + d;
        qv[d] = __bfloat162float(Qhi[qi]) + __bfloat162float(Qlo[qi]);
        o[d] = 0.f;
    }
    float l = 0.f;
    for (int c = 0; c < S_LEN; c++) {
        float s = 0.f;
        size_t kbase = (size_t)c * NKVD + hk * HD;
        for (int d = 0; d < 64; d++)
            s += qv[d] * (__bfloat162float(Khi[kbase + d]) + __bfloat162float(Klo[kbase + d]));
        float p = expf(s);
        l += p;
        for (int d = 0; d < 64; d++) {
            size_t vi = ((size_t)hk * HD + d) * S_LEN + c;
            o[d] += p * (__bfloat162float(Vthi[vi]) + __bfloat162float(Vtlo[vi]));
        }
    }
    float inv = 1.f / l;
    for (int d = 0; d < 64; d++)
        O[(size_t)t * NQD + h * HD + d] = o[d] * inv;
#endif
}

// ---------------------------------------------------------------------------
// Launch
// ---------------------------------------------------------------------------
extern "C" void kernel_launch(void* const* d_in, const int* in_sizes, int n_in,
                              void* d_out, int out_size)
{
    const float* X  = (const float*)d_in[0];
    const float* Wq = (const float*)d_in[1];
    const float* Wk = (const float*)d_in[2];
    const float* Wv = (const float*)d_in[3];
    const float* Wo = (const float*)d_in[4];
    float* out = (float*)d_out;

    float *q, *k, *v, *ctx;
    cudaGetSymbolAddress((void**)&q,   g_q);
    cudaGetSymbolAddress((void**)&k,   g_k);
    cudaGetSymbolAddress((void**)&v,   g_v);
    cudaGetSymbolAddress((void**)&ctx, g_ctx);

    __nv_bfloat16 *xhi, *xlo, *chi, *clo;
    __nv_bfloat16 *wqh, *wql, *wkh, *wkl, *wvh, *wvl, *woh, *wol;
    __nv_bfloat16 *qsh, *qsl, *ksh, *ksl, *vth, *vtl;
    cudaGetSymbolAddress((void**)&xhi, g_xhi); cudaGetSymbolAddress((void**)&xlo, g_xlo);
    cudaGetSymbolAddress((void**)&chi, g_chi); cudaGetSymbolAddress((void**)&clo, g_clo);
    cudaGetSymbolAddress((void**)&wqh, g_wqhi); cudaGetSymbolAddress((void**)&wql, g_wqlo);
    cudaGetSymbolAddress((void**)&wkh, g_wkhi); cudaGetSymbolAddress((void**)&wkl, g_wklo);
    cudaGetSymbolAddress((void**)&wvh, g_wvhi); cudaGetSymbolAddress((void**)&wvl, g_wvlo);
    cudaGetSymbolAddress((void**)&woh, g_wohi); cudaGetSymbolAddress((void**)&wol, g_wolo);
    cudaGetSymbolAddress((void**)&qsh, g_qshi); cudaGetSymbolAddress((void**)&qsl, g_qslo);
    cudaGetSymbolAddress((void**)&ksh, g_kshi); cudaGetSymbolAddress((void**)&ksl, g_kslo);
    cudaGetSymbolAddress((void**)&vth, g_vthi); cudaGetSymbolAddress((void**)&vtl, g_vtlo);

    cudaFuncSetAttribute(tc_gemm_kernel, cudaFuncAttributeMaxDynamicSharedMemorySize, GEMM_SMEM);
    cudaFuncSetAttribute(attn_tc_kernel, cudaFuncAttributeMaxDynamicSharedMemorySize, ATT_SMEM);

    // RoPE tables + GEMM operand conversion
    rope_table_kernel<<<(S_LEN * 32 + 255) / 256, 256>>>();
    convert_split_kernel<<<(S_LEN * HIDDEN + 255) / 256, 256>>>(X, xhi, xlo, S_LEN * HIDDEN);
    convert_wT_kernel<<<dim3(NQD  / 32, HIDDEN / 32), dim3(32, 8)>>>(Wq, wqh, wql, HIDDEN, NQD);
    convert_wT_kernel<<<dim3(NKVD / 32, HIDDEN / 32), dim3(32, 8)>>>(Wk, wkh, wkl, HIDDEN, NKVD);
    convert_wT_kernel<<<dim3(NKVD / 32, HIDDEN / 32), dim3(32, 8)>>>(Wv, wvh, wvl, HIDDEN, NKVD);
    convert_wT_kernel<<<dim3(HIDDEN / 32, NQD / 32),  dim3(32, 8)>>>(Wo, woh, wol, NQD, HIDDEN);

    // QKV projections
    tc_gemm_kernel<<<dim3(NQD  / 128, S_LEN / 128), 256, GEMM_SMEM>>>(xhi, xlo, wqh, wql, q, S_LEN, NQD,  HIDDEN);
    tc_gemm_kernel<<<dim3(NKVD / 128, S_LEN / 128), 256, GEMM_SMEM>>>(xhi, xlo, wkh, wkl, k, S_LEN, NKVD, HIDDEN);
    tc_gemm_kernel<<<dim3(NKVD / 128, S_LEN / 128), 256, GEMM_SMEM>>>(xhi, xlo, wvh, wvl, v, S_LEN, NKVD, HIDDEN);

    // Attention operand prep: RoPE+scale+split Q/K, transpose+split V
    prep_rope_split_kernel<<<(S_LEN * NQD / 2 + 255) / 256, 256>>>(q, qsh, qsl, NQD, 0.125f, S_LEN * NQD / 2);
    prep_rope_split_kernel<<<(S_LEN * NKVD / 2 + 255) / 256, 256>>>(k, ksh, ksl, NKVD, 1.0f, S_LEN * NKVD / 2);
    prep_vt_kernel<<<dim3(NKVD / 32, S_LEN / 32), dim3(32, 8)>>>(v, vth, vtl);

    // Fused tcgen05 flash attention
    attn_tc_kernel<<<dim3(S_LEN / 128, NH), 256, ATT_SMEM>>>(qsh, qsl, ksh, ksl, vth, vtl, ctx);

    // Output projection
    convert_split_kernel<<<(S_LEN * NQD + 255) / 256, 256>>>(ctx, chi, clo, S_LEN * NQD);
    tc_gemm_kernel<<<dim3(HIDDEN / 128, S_LEN / 128), 256, GEMM_SMEM>>>(chi, clo, woh, wol, out, S_LEN, HIDDEN, NQD);
}